// round 3
// baseline (speedup 1.0000x reference)
#include <cuda_runtime.h>
#include <cuda_bf16.h>
#include <cstdint>

// Problem constants (fixed by reference setup_inputs)
#define BB 8
#define SS 2048
#define HH 1024
#define NTOK (BB * SS)                 // 16384
#define BSS ((long long)BB * SS * SS)  // 33,554,432

// Scratch: per-token combined scores. Non-candidates encoded as -1e30 so that
// pair_score = sS + sE + bm is guaranteed <= 0 -> invalid -> outputs 0.
__device__ float g_sS[NTOK];
__device__ float g_sE[NTOK];

// ---------------------------------------------------------------------------
// Phase 1: per-token logits + scalar scores. One warp per token.
// Weights staged in shared as SoA so each lane's float4 load is at byte
// offset 16*lane within each array -> conflict-free LDS.128.
// ---------------------------------------------------------------------------
__global__ __launch_bounds__(256) void token_kernel(
    const float* __restrict__ rep,   // (B,S,H)
    const int*   __restrict__ mask,  // (B,S)
    const float* __restrict__ Ws,    // (H,2)
    const float* __restrict__ bs,    // (2,)
    const float* __restrict__ We,    // (H,2)
    const float* __restrict__ be,    // (2,)
    const float* __restrict__ Wm)    // (4,1)
{
    __shared__ float s_w0[HH];  // Ws[:,0]
    __shared__ float s_w1[HH];  // Ws[:,1]
    __shared__ float s_w2[HH];  // We[:,0]
    __shared__ float s_w3[HH];  // We[:,1]
    for (int h = threadIdx.x; h < HH; h += blockDim.x) {
        s_w0[h] = Ws[2 * h];
        s_w1[h] = Ws[2 * h + 1];
        s_w2[h] = We[2 * h];
        s_w3[h] = We[2 * h + 1];
    }
    __syncthreads();

    const int warp = threadIdx.x >> 5;
    const int lane = threadIdx.x & 31;
    const int t = blockIdx.x * 8 + warp;   // 2048 blocks * 8 warps = 16384 tokens

    const float4* __restrict__ r4 =
        reinterpret_cast<const float4*>(rep + (size_t)t * HH);

    float s0 = 0.f, s1 = 0.f, e0 = 0.f, e1 = 0.f;
#pragma unroll
    for (int it = 0; it < HH / 128; ++it) {   // 8 iterations of float4
        const int idx = it * 32 + lane;
        const float4 r  = r4[idx];
        const float4 w0 = *reinterpret_cast<const float4*>(&s_w0[idx * 4]);
        const float4 w1 = *reinterpret_cast<const float4*>(&s_w1[idx * 4]);
        const float4 w2 = *reinterpret_cast<const float4*>(&s_w2[idx * 4]);
        const float4 w3 = *reinterpret_cast<const float4*>(&s_w3[idx * 4]);
        s0 += r.x * w0.x + r.y * w0.y + r.z * w0.z + r.w * w0.w;
        s1 += r.x * w1.x + r.y * w1.y + r.z * w1.z + r.w * w1.w;
        e0 += r.x * w2.x + r.y * w2.y + r.z * w2.z + r.w * w2.w;
        e1 += r.x * w3.x + r.y * w3.y + r.z * w3.z + r.w * w3.w;
    }
#pragma unroll
    for (int off = 16; off > 0; off >>= 1) {
        s0 += __shfl_down_sync(0xFFFFFFFFu, s0, off);
        s1 += __shfl_down_sync(0xFFFFFFFFu, s1, off);
        e0 += __shfl_down_sync(0xFFFFFFFFu, e0, off);
        e1 += __shfl_down_sync(0xFFFFFFFFu, e1, off);
    }
    if (lane == 0) {
        s0 += bs[0]; s1 += bs[1];
        e0 += be[0]; e1 += be[1];
        const bool m  = (mask[t] != 0);
        const bool sc = m && (s0 <= s1);
        const bool ec = m && (e0 <= e1);
        const float score_s = s0 * Wm[0] + s1 * Wm[1];
        const float score_e = e0 * Wm[2] + e1 * Wm[3];
        g_sS[t] = sc ? score_s : -1e30f;
        g_sE[t] = ec ? score_e : -1e30f;
    }
}

// ---------------------------------------------------------------------------
// Phase 2: fill the (B,S,S) pair grid. Pure store-bandwidth kernel.
// Each thread produces 8 consecutive j cells -> 2x float4 streaming stores
// to each output. Output float4s built explicitly (no register aliasing).
// ---------------------------------------------------------------------------
__global__ __launch_bounds__(256) void pair_kernel(
    float* __restrict__ out_valid,
    float* __restrict__ out_score,
    const float* __restrict__ bm)
{
    const long long tid = (long long)blockIdx.x * blockDim.x + threadIdx.x;
    const int  jc  = (int)(tid & (SS / 8 - 1));      // 256 threads per row
    const int  j   = jc * 8;
    const long long row = tid >> 8;                  // row = b*S + i
    const int  i   = (int)(row & (SS - 1));

    const float base = g_sS[row] + bm[0];
    const long long ebase = row - i;                 // b*S
    const float4 ea = *reinterpret_cast<const float4*>(&g_sE[ebase + j]);
    const float4 eb = *reinterpret_cast<const float4*>(&g_sE[ebase + j + 4]);

    float p[8];
    p[0] = base + ea.x;  p[1] = base + ea.y;
    p[2] = base + ea.z;  p[3] = base + ea.w;
    p[4] = base + eb.x;  p[5] = base + eb.y;
    p[6] = base + eb.z;  p[7] = base + eb.w;

    float v[8], s[8];
#pragma unroll
    for (int k = 0; k < 8; ++k) {
        const bool ok = (i <= j + k) && (p[k] > 0.f);
        v[k] = ok ? 1.f : 0.f;
        s[k] = ok ? p[k] : 0.f;
    }

    const float4 v0 = make_float4(v[0], v[1], v[2], v[3]);
    const float4 v1 = make_float4(v[4], v[5], v[6], v[7]);
    const float4 s0 = make_float4(s[0], s[1], s[2], s[3]);
    const float4 s1 = make_float4(s[4], s[5], s[6], s[7]);

    const long long o = tid * 8;
    __stcs(reinterpret_cast<float4*>(out_valid + o),     v0);
    __stcs(reinterpret_cast<float4*>(out_valid + o + 4), v1);
    __stcs(reinterpret_cast<float4*>(out_score + o),     s0);
    __stcs(reinterpret_cast<float4*>(out_score + o + 4), s1);
}

extern "C" void kernel_launch(void* const* d_in, const int* in_sizes, int n_in,
                              void* d_out, int out_size)
{
    const float* rep  = (const float*)d_in[0];
    const int*   mask = (const int*)  d_in[1];
    const float* Ws   = (const float*)d_in[2];
    const float* bs   = (const float*)d_in[3];
    const float* We   = (const float*)d_in[4];
    const float* be   = (const float*)d_in[5];
    const float* Wm   = (const float*)d_in[6];
    const float* bm   = (const float*)d_in[7];

    float* out_valid = (float*)d_out;
    float* out_score = out_valid + BSS;

    // Phase 1: 16384 tokens, one warp each, 8 warps per block.
    token_kernel<<<NTOK / 8, 256>>>(rep, mask, Ws, bs, We, be, Wm);

    // Phase 2: BSS/8 threads.
    const long long nthreads = BSS / 8;
    pair_kernel<<<(unsigned)(nthreads / 256), 256>>>(out_valid, out_score, bm);
}

// round 4
// speedup vs baseline: 1.2628x; 1.2628x over previous
#include <cuda_runtime.h>
#include <cuda_bf16.h>
#include <cstdint>

// Problem constants (fixed by reference setup_inputs)
#define BB 8
#define SS 2048
#define HH 1024
#define NTOK (BB * SS)                 // 16384
#define BSS ((long long)BB * SS * SS)  // 33,554,432

// Scratch: per-token combined scores. Non-candidates encoded as -1e30 so that
// pair_score = sS + sE + bm is guaranteed <= 0 -> invalid -> outputs 0.
__device__ float g_sS[NTOK];
__device__ float g_sE[NTOK];

// ---------------------------------------------------------------------------
// Phase 1: per-token logits + scalar scores. Two tokens per warp, loads
// front-batched for 16 outstanding LDG.128 per warp. Weights staged in
// shared as SoA -> conflict-free LDS.128.
// ---------------------------------------------------------------------------
__global__ __launch_bounds__(256) void token_kernel(
    const float* __restrict__ rep,   // (B,S,H)
    const int*   __restrict__ mask,  // (B,S)
    const float* __restrict__ Ws,    // (H,2)
    const float* __restrict__ bs,    // (2,)
    const float* __restrict__ We,    // (H,2)
    const float* __restrict__ be,    // (2,)
    const float* __restrict__ Wm)    // (4,1)
{
    __shared__ float s_w0[HH];  // Ws[:,0]
    __shared__ float s_w1[HH];  // Ws[:,1]
    __shared__ float s_w2[HH];  // We[:,0]
    __shared__ float s_w3[HH];  // We[:,1]
    for (int h = threadIdx.x; h < HH; h += blockDim.x) {
        s_w0[h] = Ws[2 * h];
        s_w1[h] = Ws[2 * h + 1];
        s_w2[h] = We[2 * h];
        s_w3[h] = We[2 * h + 1];
    }
    __syncthreads();

    const int warp = threadIdx.x >> 5;
    const int lane = threadIdx.x & 31;
    // 1024 blocks * 8 warps * 2 tokens = 16384 tokens
    const int tA = blockIdx.x * 16 + warp * 2;
    const int tB = tA + 1;

    const float4* __restrict__ rA4 =
        reinterpret_cast<const float4*>(rep + (size_t)tA * HH);
    const float4* __restrict__ rB4 =
        reinterpret_cast<const float4*>(rep + (size_t)tB * HH);

    // Front-batch all global loads (16 LDG.128 in flight).
    float4 ra[8], rb[8];
#pragma unroll
    for (int it = 0; it < 8; ++it) {
        ra[it] = rA4[it * 32 + lane];
        rb[it] = rB4[it * 32 + lane];
    }

    float as0 = 0.f, as1 = 0.f, ae0 = 0.f, ae1 = 0.f;
    float bs0_ = 0.f, bs1_ = 0.f, be0_ = 0.f, be1_ = 0.f;
#pragma unroll
    for (int it = 0; it < 8; ++it) {
        const int idx = it * 32 + lane;
        const float4 w0 = *reinterpret_cast<const float4*>(&s_w0[idx * 4]);
        const float4 w1 = *reinterpret_cast<const float4*>(&s_w1[idx * 4]);
        const float4 w2 = *reinterpret_cast<const float4*>(&s_w2[idx * 4]);
        const float4 w3 = *reinterpret_cast<const float4*>(&s_w3[idx * 4]);
        const float4 a = ra[it];
        const float4 b = rb[it];
        as0 += a.x * w0.x + a.y * w0.y + a.z * w0.z + a.w * w0.w;
        as1 += a.x * w1.x + a.y * w1.y + a.z * w1.z + a.w * w1.w;
        ae0 += a.x * w2.x + a.y * w2.y + a.z * w2.z + a.w * w2.w;
        ae1 += a.x * w3.x + a.y * w3.y + a.z * w3.z + a.w * w3.w;
        bs0_ += b.x * w0.x + b.y * w0.y + b.z * w0.z + b.w * w0.w;
        bs1_ += b.x * w1.x + b.y * w1.y + b.z * w1.z + b.w * w1.w;
        be0_ += b.x * w2.x + b.y * w2.y + b.z * w2.z + b.w * w2.w;
        be1_ += b.x * w3.x + b.y * w3.y + b.z * w3.z + b.w * w3.w;
    }
#pragma unroll
    for (int off = 16; off > 0; off >>= 1) {
        as0 += __shfl_down_sync(0xFFFFFFFFu, as0, off);
        as1 += __shfl_down_sync(0xFFFFFFFFu, as1, off);
        ae0 += __shfl_down_sync(0xFFFFFFFFu, ae0, off);
        ae1 += __shfl_down_sync(0xFFFFFFFFu, ae1, off);
        bs0_ += __shfl_down_sync(0xFFFFFFFFu, bs0_, off);
        bs1_ += __shfl_down_sync(0xFFFFFFFFu, bs1_, off);
        be0_ += __shfl_down_sync(0xFFFFFFFFu, be0_, off);
        be1_ += __shfl_down_sync(0xFFFFFFFFu, be1_, off);
    }
    if (lane == 0) {
        const float wm0 = Wm[0], wm1 = Wm[1], wm2 = Wm[2], wm3 = Wm[3];
        const float b0 = bs[0], b1 = bs[1], b2 = be[0], b3 = be[1];
        {
            const float s0 = as0 + b0, s1 = as1 + b1;
            const float e0 = ae0 + b2, e1 = ae1 + b3;
            const bool m  = (mask[tA] != 0);
            g_sS[tA] = (m && s0 <= s1) ? (s0 * wm0 + s1 * wm1) : -1e30f;
            g_sE[tA] = (m && e0 <= e1) ? (e0 * wm2 + e1 * wm3) : -1e30f;
        }
        {
            const float s0 = bs0_ + b0, s1 = bs1_ + b1;
            const float e0 = be0_ + b2, e1 = be1_ + b3;
            const bool m  = (mask[tB] != 0);
            g_sS[tB] = (m && s0 <= s1) ? (s0 * wm0 + s1 * wm1) : -1e30f;
            g_sE[tB] = (m && e0 <= e1) ? (e0 * wm2 + e1 * wm3) : -1e30f;
        }
    }
}

// ---------------------------------------------------------------------------
// Phase 2: fill the (B,S,S) pair grid. Pure store-bandwidth kernel.
// Each thread produces 4 consecutive j cells -> float4 stores to both
// outputs (R1 form: plain stores, 4 el/thread — measured fastest).
// ---------------------------------------------------------------------------
__global__ __launch_bounds__(256) void pair_kernel(
    float* __restrict__ out_valid,
    float* __restrict__ out_score,
    const float* __restrict__ bm)
{
    const long long tid = (long long)blockIdx.x * blockDim.x + threadIdx.x;
    const int  j   = (int)(tid & (SS / 4 - 1)) * 4;  // 512 threads per row
    const long long row = tid >> 9;                  // row = b*S + i
    const int  i   = (int)(row & (SS - 1));

    const float sSv = g_sS[row];
    const long long ebase = row - i;                 // b*S
    const float4 ev = *reinterpret_cast<const float4*>(&g_sE[ebase + j]);
    const float bmv = bm[0];

    float p0 = sSv + ev.x + bmv;
    float p1 = sSv + ev.y + bmv;
    float p2 = sSv + ev.z + bmv;
    float p3 = sSv + ev.w + bmv;

    const bool v0 = (i <= j + 0) && (p0 > 0.f);
    const bool v1 = (i <= j + 1) && (p1 > 0.f);
    const bool v2 = (i <= j + 2) && (p2 > 0.f);
    const bool v3 = (i <= j + 3) && (p3 > 0.f);

    float4 vo, so;
    vo.x = v0 ? 1.f : 0.f;  so.x = v0 ? p0 : 0.f;
    vo.y = v1 ? 1.f : 0.f;  so.y = v1 ? p1 : 0.f;
    vo.z = v2 ? 1.f : 0.f;  so.z = v2 ? p2 : 0.f;
    vo.w = v3 ? 1.f : 0.f;  so.w = v3 ? p3 : 0.f;

    const long long o = tid * 4;
    *reinterpret_cast<float4*>(out_valid + o) = vo;
    *reinterpret_cast<float4*>(out_score + o) = so;
}

extern "C" void kernel_launch(void* const* d_in, const int* in_sizes, int n_in,
                              void* d_out, int out_size)
{
    const float* rep  = (const float*)d_in[0];
    const int*   mask = (const int*)  d_in[1];
    const float* Ws   = (const float*)d_in[2];
    const float* bs   = (const float*)d_in[3];
    const float* We   = (const float*)d_in[4];
    const float* be   = (const float*)d_in[5];
    const float* Wm   = (const float*)d_in[6];
    const float* bm   = (const float*)d_in[7];

    float* out_valid = (float*)d_out;
    float* out_score = out_valid + BSS;

    // Phase 1: 16384 tokens, two per warp, 8 warps per block.
    token_kernel<<<NTOK / 16, 256>>>(rep, mask, Ws, bs, We, be, Wm);

    // Phase 2: BSS/4 threads.
    const long long nthreads = BSS / 4;
    pair_kernel<<<(unsigned)(nthreads / 256), 256>>>(out_valid, out_score, bm);
}